// round 5
// baseline (speedup 1.0000x reference)
#include <cuda_runtime.h>

// Problem constants: x [B=8, C=64, T=32, H=56, W=56], window 7, eps 1e-5.
#define BB   8
#define CC   64
#define TT   32
#define HWV  (56 * 56)       // 3136 spatial positions
#define HW4  (HWV / 4)       // 784 float4 per (b,c,t)
#define NBC  (BB * CC)       // 512 (b,c) slabs
#define NPC  ((double)(BB * TT * HWV))  // 802816 elements per channel

// Deterministic scratch (no atomics): per-(b,c)-block partial sums, then
// per-channel affine coefficients. __device__ globals per allocation rules.
__device__ double g_psum[NBC];
__device__ double g_psumsq[NBC];
__device__ float  g_scale[CC];
__device__ float  g_bias[CC];
__device__ float  g_k[2];

// rank-pool coefficient dot: win[k] = x[t-6+k], coeff[k] = 2k-6
// rp = 2*(3*(w6-w0) + 2*(w5-w1) + (w4-w2))
#define RP_COMP(comp, xv)                                                     \
    (2.0f * (3.0f * ((xv).comp - w0.comp) + 2.0f * (w5.comp - w1.comp) +      \
             (w4.comp - w2.comp)))

// ---------------- Pass 1: rp + per-channel sum / sumsq ----------------
__global__ __launch_bounds__(256) void datt_pass1(const float* __restrict__ x) {
    const int bc = blockIdx.x;
    const float4* __restrict__ base =
        reinterpret_cast<const float4*>(x) + (size_t)bc * TT * HW4;

    float s = 0.0f, ss = 0.0f;

    for (int p = threadIdx.x; p < HW4; p += 256) {
        const float4* q = base + p;
        float4 w0 = {0.f, 0.f, 0.f, 0.f};
        float4 w1 = w0, w2 = w0, w3 = w0, w4 = w0, w5 = w0;
#pragma unroll
        for (int t = 0; t < TT; t++) {
            float4 xv = q[t * HW4];
            float rx = RP_COMP(x, xv);
            float ry = RP_COMP(y, xv);
            float rz = RP_COMP(z, xv);
            float rw = RP_COMP(w, xv);
            s += (rx + ry) + (rz + rw);
            ss = fmaf(rx, rx, ss);
            ss = fmaf(ry, ry, ss);
            ss = fmaf(rz, rz, ss);
            ss = fmaf(rw, rw, ss);
            w0 = w1; w1 = w2; w2 = w3; w3 = w4; w4 = w5; w5 = xv;
        }
    }

    // Block reduction in double (deterministic; one slot per block).
    double ds = (double)s, dss = (double)ss;
#pragma unroll
    for (int o = 16; o > 0; o >>= 1) {
        ds  += __shfl_down_sync(0xFFFFFFFFu, ds, o);
        dss += __shfl_down_sync(0xFFFFFFFFu, dss, o);
    }
    __shared__ double sh_s[8], sh_ss[8];
    const int lane = threadIdx.x & 31, wid = threadIdx.x >> 5;
    if (lane == 0) { sh_s[wid] = ds; sh_ss[wid] = dss; }
    __syncthreads();
    if (threadIdx.x == 0) {
        double a = 0.0, b = 0.0;
#pragma unroll
        for (int i = 0; i < 8; i++) { a += sh_s[i]; b += sh_ss[i]; }
        g_psum[bc]   = a;
        g_psumsq[bc] = b;
    }
}

// ---------------- Finalize: per-channel BN affine + mix constants ----------------
__global__ void datt_finalize(const float* __restrict__ gamma,
                              const float* __restrict__ beta,
                              const float* __restrict__ rpw) {
    const int c = threadIdx.x;
    if (c < CC) {
        double a = 0.0, b = 0.0;
#pragma unroll
        for (int bb = 0; bb < BB; bb++) {
            a += g_psum[bb * CC + c];
            b += g_psumsq[bb * CC + c];
        }
        const double mean = a / NPC;
        const double var  = b / NPC - mean * mean;
        const double sc   = (double)gamma[c] / sqrt(var + 1e-5);
        g_scale[c] = (float)sc;
        g_bias[c]  = (float)((double)beta[c] - mean * sc);
    }
    if (c == 0) {
        g_k[0] = rpw[0] + rpw[1];  // k1
        g_k[1] = rpw[1];           // k2
    }
}

// ---------------- Pass 2: recompute rp, BN+ReLU+gate+mix, write ----------------
// out = x * (k1 + k2 * relu(sc*rp + bi))
__global__ __launch_bounds__(256) void datt_pass2(const float* __restrict__ x,
                                                  float* __restrict__ out) {
    // Reverse bc order: first-scheduled pass2 blocks hit the slabs pass1
    // touched last, which are still resident in the 126 MB L2.
    const int bc = (NBC - 1) - blockIdx.x;
    const int c  = bc & (CC - 1);
    const float sc = g_scale[c];
    const float bi = g_bias[c];
    const float k1 = g_k[0];
    const float k2 = g_k[1];

    const float4* __restrict__ base =
        reinterpret_cast<const float4*>(x) + (size_t)bc * TT * HW4;
    float4* __restrict__ ob =
        reinterpret_cast<float4*>(out) + (size_t)bc * TT * HW4;

    for (int p = threadIdx.x; p < HW4; p += 256) {
        const float4* q = base + p;
        float4* o = ob + p;
        float4 w0 = {0.f, 0.f, 0.f, 0.f};
        float4 w1 = w0, w2 = w0, w3 = w0, w4 = w0, w5 = w0;
#pragma unroll
        for (int t = 0; t < TT; t++) {
            float4 xv = __ldcs(q + t * HW4);  // streaming: last use of x
            float rx = RP_COMP(x, xv);
            float ry = RP_COMP(y, xv);
            float rz = RP_COMP(z, xv);
            float rw = RP_COMP(w, xv);
            float yx = fmaxf(fmaf(rx, sc, bi), 0.0f);
            float yy = fmaxf(fmaf(ry, sc, bi), 0.0f);
            float yz = fmaxf(fmaf(rz, sc, bi), 0.0f);
            float yw = fmaxf(fmaf(rw, sc, bi), 0.0f);
            float4 ov;
            ov.x = xv.x * fmaf(k2, yx, k1);
            ov.y = xv.y * fmaf(k2, yy, k1);
            ov.z = xv.z * fmaf(k2, yz, k1);
            ov.w = xv.w * fmaf(k2, yw, k1);
            __stcs(o + t * HW4, ov);          // streaming store
            w0 = w1; w1 = w2; w2 = w3; w3 = w4; w4 = w5; w5 = xv;
        }
    }
}

extern "C" void kernel_launch(void* const* d_in, const int* in_sizes, int n_in,
                              void* d_out, int out_size) {
    const float* x     = (const float*)d_in[0];  // [8,64,32,56,56]
    const float* gamma = (const float*)d_in[1];  // [64]
    const float* beta  = (const float*)d_in[2];  // [64]
    const float* rpw   = (const float*)d_in[3];  // [2]
    // d_in[4] is the window size w (== 7), compiled in.
    float* out = (float*)d_out;

    datt_pass1<<<NBC, 256>>>(x);
    datt_finalize<<<1, 64>>>(gamma, beta, rpw);
    datt_pass2<<<NBC, 256>>>(x, out);
}